// round 15
// baseline (speedup 1.0000x reference)
#include <cuda_runtime.h>
#include <cuda_fp16.h>
#include <stdint.h>

#define N_NODES 100000
#define N_EDGES 3200000
#define TOT_EDGES (N_EDGES + N_NODES)
#define F_IN 256
#define HID 64
#define C_OUT 2
#define G_GRAPHS 128

#define SCAN_BLK 1024
#define SCAN_NB ((N_NODES + SCAN_BLK - 1) / SCAN_BLK)

// ---------------- scratch: __device__ globals ----------------
__device__ __half g_hxh[(size_t)N_NODES * HID];   // GEMM output, pre-scaled by isq[src] (fp16)
__device__ __half g_h [(size_t)N_NODES * HID];    // agg1 output (fp16, read only by GEMM2)
__device__ float  g_isq[N_NODES];
__device__ int    g_deg[N_NODES];                 // zero at entry, zero at exit
__device__ int    g_rowptr[N_NODES + 1];
__device__ int    g_cursor[N_NODES];
__device__ int    g_eidx[TOT_EDGES];
__device__ int    g_bsum[SCAN_NB + 1];
__device__ float  g_pool[G_GRAPHS * HID];
__device__ float  g_pcnt[G_GRAPHS];
__device__ int    g_is64;
__device__ __half g_W1t[64 * 256];                // W1 transposed, fp16: [n][k]
__device__ __half g_W2t[64 * 64];                 // W2 transposed, fp16: [n][k]

__device__ __forceinline__ int ld_idx(const void* p, size_t i) {
    if (g_is64) return (int)((const long long*)p)[i];
    return ((const int*)p)[i];
}

// ---------------- fused prologue: detect + W transpose + pool init + degree histogram ----------------
#define SETUP_DEG_BASE (1 + 64 + ((N_NODES + 255) / 256))   // 456
__global__ void k_setup(const int* __restrict__ ei_raw,
                        const float* __restrict__ W1, const float* __restrict__ W2) {
    int b = blockIdx.x;
    int tid = threadIdx.x;
    if (b == 0) {
        __shared__ int s_or[256];
        int acc = 0;
#pragma unroll
        for (int i = 0; i < 32; i++) acc |= ei_raw[2 * (tid + i * 256) + 1];
        s_or[tid] = acc;
        __syncthreads();
        for (int off = 128; off > 0; off >>= 1) {
            if (tid < off) s_or[tid] |= s_or[tid + off];
            __syncthreads();
        }
        if (tid == 0) g_is64 = (s_or[0] == 0) ? 1 : 0;
    } else if (b <= 64) {
        int i = (b - 1) * 256 + tid;
        {   int n = i >> 8, k = i & 255;
            g_W1t[i] = __float2half_rn(W1[k * 64 + n]); }
        if (i < 64 * 64) {
            int n = i >> 6, k = i & 63;
            g_W2t[i] = __float2half_rn(W2[k * 64 + n]); }
    } else if (b < SETUP_DEG_BASE) {
        int i = (b - 65) * 256 + tid;
        if (i < G_GRAPHS * HID) g_pool[i] = 0.f;
        if (i < G_GRAPHS) g_pcnt[i] = 0.f;
    } else {
        // per-block local dtype detect (no same-kernel race on g_is64)
        int lane = tid & 31;
        int probe = ei_raw[2 * lane + 1];
        bool is64 = !__any_sync(0xffffffffu, probe != 0);
        int e = (b - SETUP_DEG_BASE) * 256 + tid;
        if (e < N_EDGES) {
            int d = is64 ? (int)((const long long*)ei_raw)[(size_t)N_EDGES + e]
                         : ei_raw[(size_t)N_EDGES + e];
            atomicAdd(&g_deg[d], 1);
        }
    }
}

// ---------------- scan phase 1: per-block inclusive scan of (deg + 1 self-loop) ----------------
__global__ void k_scan1() {
    __shared__ int s[SCAN_BLK];
    int tid = threadIdx.x;
    int i = blockIdx.x * SCAN_BLK + tid;
    int v = (i < N_NODES) ? (g_deg[i] + 1) : 0;
    s[tid] = v;
    __syncthreads();
    for (int off = 1; off < SCAN_BLK; off <<= 1) {
        int t = (tid >= off) ? s[tid - off] : 0;
        __syncthreads();
        s[tid] += t;
        __syncthreads();
    }
    if (i < N_NODES) g_cursor[i] = s[tid];
    if (tid == SCAN_BLK - 1) g_bsum[blockIdx.x] = s[tid];
}

// ---------------- scan phase 2 ----------------
__global__ void k_scan2() {
    __shared__ int s[128];
    int tid = threadIdx.x;
    int v = (tid < SCAN_NB) ? g_bsum[tid] : 0;
    s[tid] = v;
    __syncthreads();
#pragma unroll
    for (int off = 1; off < 128; off <<= 1) {
        int t = (tid >= off) ? s[tid - off] : 0;
        __syncthreads();
        s[tid] += t;
        __syncthreads();
    }
    if (tid < SCAN_NB) g_bsum[tid] = s[tid] - v;
    if (tid == 127) g_rowptr[N_NODES] = s[127];
}

// ---------------- scan phase 3: finalize + self-clean g_deg ----------------
__global__ void k_scan3() {
    int i = blockIdx.x * blockDim.x + threadIdx.x;
    if (i >= N_NODES) return;
    int incl = g_cursor[i] + g_bsum[i / SCAN_BLK];
    g_rowptr[i + 1] = incl;
    int d = g_deg[i] + 1;
    g_deg[i] = 0;
    g_cursor[i] = incl - d;
    g_isq[i] = rsqrtf((float)d);
    if (i == 0) g_rowptr[0] = 0;
}

// ---------------- fill CSR ----------------
__global__ void k_fill(const void* __restrict__ ei) {
    int t = blockIdx.x * blockDim.x + threadIdx.x;
    if (t >= TOT_EDGES) return;
    int s, d;
    if (t < N_EDGES) {
        s = ld_idx(ei, t);
        d = ld_idx(ei, (size_t)N_EDGES + t);
    } else {
        s = d = t - N_EDGES;
    }
    int pos = atomicAdd(&g_cursor[d], 1);
    g_eidx[pos] = s;
}

// ---------------- tensor-core GEMM: g_hxh[N,64] = fp16(isq[n] * (X[N,K] @ W[K,64])) ----------------
template <int K, int LAYER>
__global__ void k_gemm_mma(const float* __restrict__ Xin) {
    constexpr int CK = 64;
    constexpr int APAD = 72;
    constexpr int WPAD = K + 8;
    __shared__ __half sX[128 * APAD];
    __shared__ __half sWt[64 * WPAD];

    const __half* Wt = (LAYER == 1) ? g_W1t : g_W2t;
    int tid = threadIdx.x;
    int wid = tid >> 5, lane = tid & 31;
    int g = lane >> 2, tig = lane & 3;
    int nodeBase = blockIdx.x * 128;

    for (int i = tid; i < 64 * (K / 2); i += 256) {
        int n = i / (K / 2), kw = i % (K / 2);
        ((uint32_t*)sWt)[n * (WPAD / 2) + kw] = ((const uint32_t*)Wt)[n * (K / 2) + kw];
    }

    float acc[8][4];
#pragma unroll
    for (int nt = 0; nt < 8; nt++)
#pragma unroll
        for (int j = 0; j < 4; j++) acc[nt][j] = 0.f;

    for (int kk = 0; kk < K; kk += CK) {
        for (int i = tid; i < 128 * (CK / 2); i += 256) {
            int row = i >> 5;
            int c2 = i & 31;
            int node = nodeBase + row;
            __half2 hv;
            if (LAYER == 1) {
                float2 v = (node < N_NODES)
                    ? *(const float2*)&Xin[(size_t)node * K + kk + c2 * 2]
                    : make_float2(0.f, 0.f);
                hv = __floats2half2_rn(v.x, v.y);
            } else {
                hv = (node < N_NODES)
                    ? ((const __half2*)g_h)[(size_t)node * (K / 2) + (kk / 2) + c2]
                    : __halves2half2(__float2half_rn(0.f), __float2half_rn(0.f));
            }
            ((__half2*)sX)[row * (APAD / 2) + c2] = hv;
        }
        __syncthreads();

        int mrow = wid * 16;
#pragma unroll
        for (int kt = 0; kt < CK / 16; kt++) {
            int k0 = kt * 16;
            uint32_t a0 = *(const uint32_t*)&sX[(mrow + g    ) * APAD + k0     + 2 * tig];
            uint32_t a1 = *(const uint32_t*)&sX[(mrow + g + 8) * APAD + k0     + 2 * tig];
            uint32_t a2 = *(const uint32_t*)&sX[(mrow + g    ) * APAD + k0 + 8 + 2 * tig];
            uint32_t a3 = *(const uint32_t*)&sX[(mrow + g + 8) * APAD + k0 + 8 + 2 * tig];
#pragma unroll
            for (int nt = 0; nt < 8; nt++) {
                uint32_t b0 = *(const uint32_t*)&sWt[(nt * 8 + g) * WPAD + kk + k0     + 2 * tig];
                uint32_t b1 = *(const uint32_t*)&sWt[(nt * 8 + g) * WPAD + kk + k0 + 8 + 2 * tig];
                asm volatile(
                    "mma.sync.aligned.m16n8k16.row.col.f32.f16.f16.f32 "
                    "{%0,%1,%2,%3}, {%4,%5,%6,%7}, {%8,%9}, {%0,%1,%2,%3};\n"
                    : "+f"(acc[nt][0]), "+f"(acc[nt][1]), "+f"(acc[nt][2]), "+f"(acc[nt][3])
                    : "r"(a0), "r"(a1), "r"(a2), "r"(a3), "r"(b0), "r"(b1));
            }
        }
        __syncthreads();
    }

    int r0 = nodeBase + wid * 16 + g;
    float s0 = (r0 < N_NODES) ? g_isq[r0] : 0.f;
    float s1 = (r0 + 8 < N_NODES) ? g_isq[r0 + 8] : 0.f;
#pragma unroll
    for (int nt = 0; nt < 8; nt++) {
        if (r0 < N_NODES)
            *(__half2*)&g_hxh[(size_t)r0 * 64 + nt * 8 + 2 * tig] =
                __floats2half2_rn(acc[nt][0] * s0, acc[nt][1] * s0);
        if (r0 + 8 < N_NODES)
            *(__half2*)&g_hxh[(size_t)(r0 + 8) * 64 + nt * 8 + 2 * tig] =
                __floats2half2_rn(acc[nt][2] * s1, acc[nt][3] * s1);
    }
}

// ---------------- pull aggregation: warp/node, 8-way unrolled independent gathers ----------------
template <bool FUSE_POOL>
__global__ void k_agg(const float* __restrict__ bias, const void* __restrict__ batch) {
    int gt = blockIdx.x * blockDim.x + threadIdx.x;
    int node = gt >> 5;
    int lane = gt & 31;
    int wid = threadIdx.x >> 5;

    if (!FUSE_POOL && node >= N_NODES) return;

    int r0 = g_rowptr[node];
    int r1 = g_rowptr[node + 1];
    const __half2* h2 = (const __half2*)g_hxh;

    float ax0 = 0.f, ay0 = 0.f, ax1 = 0.f, ay1 = 0.f;
    float ax2 = 0.f, ay2 = 0.f, ax3 = 0.f, ay3 = 0.f;

    int e = r0;
    for (; e + 8 <= r1; e += 8) {
        int s0 = g_eidx[e    ];
        int s1 = g_eidx[e + 1];
        int s2 = g_eidx[e + 2];
        int s3 = g_eidx[e + 3];
        int s4 = g_eidx[e + 4];
        int s5 = g_eidx[e + 5];
        int s6 = g_eidx[e + 6];
        int s7 = g_eidx[e + 7];
        float2 v0 = __half22float2(h2[(size_t)s0 * 32 + lane]);
        float2 v1 = __half22float2(h2[(size_t)s1 * 32 + lane]);
        float2 v2 = __half22float2(h2[(size_t)s2 * 32 + lane]);
        float2 v3 = __half22float2(h2[(size_t)s3 * 32 + lane]);
        float2 v4 = __half22float2(h2[(size_t)s4 * 32 + lane]);
        float2 v5 = __half22float2(h2[(size_t)s5 * 32 + lane]);
        float2 v6 = __half22float2(h2[(size_t)s6 * 32 + lane]);
        float2 v7 = __half22float2(h2[(size_t)s7 * 32 + lane]);
        ax0 += v0.x; ay0 += v0.y;
        ax1 += v1.x; ay1 += v1.y;
        ax2 += v2.x; ay2 += v2.y;
        ax3 += v3.x; ay3 += v3.y;
        ax0 += v4.x; ay0 += v4.y;
        ax1 += v5.x; ay1 += v5.y;
        ax2 += v6.x; ay2 += v6.y;
        ax3 += v7.x; ay3 += v7.y;
    }
    for (; e < r1; e++) {
        int s = g_eidx[e];
        float2 v = __half22float2(h2[(size_t)s * 32 + lane]);
        ax0 += v.x; ay0 += v.y;
    }
    float ax = (ax0 + ax1) + (ax2 + ax3);
    float ay = (ay0 + ay1) + (ay2 + ay3);

    float wd = g_isq[node];
    float ox = fmaxf(ax * wd + bias[2 * lane + 0], 0.f);
    float oy = fmaxf(ay * wd + bias[2 * lane + 1], 0.f);

    if (!FUSE_POOL) {
        ((__half2*)g_h)[(size_t)node * 32 + lane] = __floats2half2_rn(ox, oy);
    } else {
        __shared__ float s_pool[64];
        __shared__ int s_g[8];
        int gph = ld_idx(batch, node);
        if (lane == 0) s_g[wid] = gph;
        if (threadIdx.x < 64) s_pool[threadIdx.x] = 0.f;
        __syncthreads();
        if (s_g[0] == s_g[7]) {
            atomicAdd(&s_pool[2 * lane + 0], ox);
            atomicAdd(&s_pool[2 * lane + 1], oy);
            __syncthreads();
            if (threadIdx.x < 64) atomicAdd(&g_pool[s_g[0] * 64 + threadIdx.x], s_pool[threadIdx.x]);
            if (threadIdx.x == 0) atomicAdd(&g_pcnt[s_g[0]], 8.f);
        } else {
            atomicAdd(&g_pool[gph * 64 + 2 * lane + 0], ox);
            atomicAdd(&g_pool[gph * 64 + 2 * lane + 1], oy);
            if (lane == 0) atomicAdd(&g_pcnt[gph], 1.f);
        }
    }
}

// ---------------- final FC ----------------
__global__ void k_fc(const float* __restrict__ fcW, const float* __restrict__ fcb,
                     float* __restrict__ out) {
    int g = threadIdx.x;
    if (g >= G_GRAPHS) return;
    float cnt = g_pcnt[g];
    float inv = 1.f / fmaxf(cnt, 1.f);
    float a0 = fcb[0], a1 = fcb[1];
#pragma unroll
    for (int h = 0; h < 64; h++) {
        float p = g_pool[g * 64 + h] * inv;
        a0 += p * fcW[h * 2 + 0];
        a1 += p * fcW[h * 2 + 1];
    }
    out[g * 2 + 0] = a0;
    out[g * 2 + 1] = a1;
}

// ---------------- launch: fork fill ∥ GEMM1 via per-thread stream + events ----------------
extern "C" void kernel_launch(void* const* d_in, const int* in_sizes, int n_in,
                              void* d_out, int out_size) {
    const float* x    = (const float*)d_in[0];
    const void*  ei   = d_in[1];
    const void*  bat  = d_in[2];
    const float* W1   = (const float*)d_in[3];
    const float* b1   = (const float*)d_in[4];
    const float* W2   = (const float*)d_in[5];
    const float* b2   = (const float*)d_in[6];
    const float* fcW  = (const float*)d_in[7];
    const float* fcb  = (const float*)d_in[8];
    float* out = (float*)d_out;

    // host-side sync objects (no device memory); created once, identical captured
    // work on every call
    static cudaEvent_t evFork = nullptr, evJoin = nullptr;
    if (evFork == nullptr) {
        cudaEventCreateWithFlags(&evFork, cudaEventDisableTiming);
        cudaEventCreateWithFlags(&evJoin, cudaEventDisableTiming);
    }

    const int TPB = 256;
    int gN = (N_NODES + TPB - 1) / TPB;              // 391
    int gE = (N_EDGES + TPB - 1) / TPB;              // 12500
    int gTOT = (TOT_EDGES + TPB - 1) / TPB;          // 12892
    int gW = (N_NODES * 32) / TPB;                   // 12500 exactly
    int gM = (N_NODES + 127) / 128;                  // 782

    k_setup<<<SETUP_DEG_BASE + gE, TPB>>>((const int*)ei, W1, W2);
    k_scan1<<<SCAN_NB, SCAN_BLK>>>();
    k_scan2<<<1, 128>>>();
    k_scan3<<<gN, TPB>>>();

    // fork: GEMM1 (needs isq + Wt) runs on the per-thread stream,
    // concurrently with k_fill (needs cursor) on the legacy stream.
    cudaEventRecord(evFork, 0);
    cudaStreamWaitEvent(cudaStreamPerThread, evFork, 0);
    k_gemm_mma<F_IN, 1><<<gM, TPB, 0, cudaStreamPerThread>>>(x);
    k_fill<<<gTOT, TPB>>>(ei);
    cudaEventRecord(evJoin, cudaStreamPerThread);
    cudaStreamWaitEvent(0, evJoin, 0);

    // join: AGG1 needs both g_eidx (fill) and g_hxh (GEMM1)
    k_agg<false><<<gW, TPB>>>(b1, nullptr);
    k_gemm_mma<HID, 2><<<gM, TPB>>>(nullptr);
    k_agg<true><<<gW, TPB>>>(b2, bat);
    k_fc<<<1, 128>>>(fcW, fcb, out);
}

// round 16
// speedup vs baseline: 1.0042x; 1.0042x over previous
#include <cuda_runtime.h>
#include <cuda_fp16.h>
#include <stdint.h>

#define N_NODES 100000
#define N_EDGES 3200000
#define TOT_EDGES (N_EDGES + N_NODES)
#define F_IN 256
#define HID 64
#define C_OUT 2
#define G_GRAPHS 128

#define SCAN_BLK 1024
#define SCAN_NB ((N_NODES + SCAN_BLK - 1) / SCAN_BLK)   // 98

// ---------------- scratch: __device__ globals ----------------
__device__ __half g_hxh[(size_t)N_NODES * HID];   // GEMM output, pre-scaled by isq[src] (fp16)
__device__ __half g_h [(size_t)N_NODES * HID];    // agg1 output (fp16, read only by GEMM2)
__device__ float  g_isq[N_NODES];
__device__ int    g_deg[N_NODES];                 // zero at entry, zero at exit
__device__ int    g_rowptr[N_NODES + 1];
__device__ int    g_cursor[N_NODES];
__device__ int    g_eidx[TOT_EDGES];
__device__ unsigned long long g_scanst[SCAN_NB];  // lookback status: zeroed by k_setup each call
__device__ float  g_pool[G_GRAPHS * HID];
__device__ float  g_pcnt[G_GRAPHS];
__device__ int    g_is64;
__device__ __half g_W1t[64 * 256];                // W1 transposed, fp16: [n][k]
__device__ __half g_W2t[64 * 64];                 // W2 transposed, fp16: [n][k]

__device__ __forceinline__ int ld_idx(const void* p, size_t i) {
    if (g_is64) return (int)((const long long*)p)[i];
    return ((const int*)p)[i];
}

// ---------------- fused prologue: detect + W transpose + init + degree histogram ----------------
#define SETUP_DEG_BASE (1 + 64 + ((N_NODES + 255) / 256))   // 456
__global__ void k_setup(const int* __restrict__ ei_raw,
                        const float* __restrict__ W1, const float* __restrict__ W2) {
    int b = blockIdx.x;
    int tid = threadIdx.x;
    if (b == 0) {
        __shared__ int s_or[256];
        int acc = 0;
#pragma unroll
        for (int i = 0; i < 32; i++) acc |= ei_raw[2 * (tid + i * 256) + 1];
        s_or[tid] = acc;
        __syncthreads();
        for (int off = 128; off > 0; off >>= 1) {
            if (tid < off) s_or[tid] |= s_or[tid + off];
            __syncthreads();
        }
        if (tid == 0) g_is64 = (s_or[0] == 0) ? 1 : 0;
    } else if (b <= 64) {
        int i = (b - 1) * 256 + tid;
        {   int n = i >> 8, k = i & 255;
            g_W1t[i] = __float2half_rn(W1[k * 64 + n]); }
        if (i < 64 * 64) {
            int n = i >> 6, k = i & 63;
            g_W2t[i] = __float2half_rn(W2[k * 64 + n]); }
    } else if (b < SETUP_DEG_BASE) {
        int i = (b - 65) * 256 + tid;
        if (i < G_GRAPHS * HID) g_pool[i] = 0.f;
        if (i < G_GRAPHS) g_pcnt[i] = 0.f;
        if (b == 65 && tid < SCAN_NB) g_scanst[tid] = 0ULL;   // reset lookback flags
    } else {
        // per-block local dtype detect (no same-kernel race on g_is64)
        int lane = tid & 31;
        int probe = ei_raw[2 * lane + 1];
        bool is64 = !__any_sync(0xffffffffu, probe != 0);
        int e = (b - SETUP_DEG_BASE) * 256 + tid;
        if (e < N_EDGES) {
            int d = is64 ? (int)((const long long*)ei_raw)[(size_t)N_EDGES + e]
                         : ei_raw[(size_t)N_EDGES + e];
            atomicAdd(&g_deg[d], 1);
        }
    }
}

// ---------------- single-pass scan: decoupled lookback + finalize ----------------
// Computes rowptr/cursor/isq from g_deg (+1 self loop), self-cleans g_deg.
// 98 blocks <= 148 SMs: all resident; lookback is strictly backward (no deadlock).
__device__ __forceinline__ unsigned long long pack_st(unsigned flag, unsigned val) {
    return ((unsigned long long)flag << 32) | val;
}
__global__ void k_scan() {
    __shared__ int s[SCAN_BLK];
    __shared__ int s_excl;
    int tid = threadIdx.x;
    int b = blockIdx.x;
    int i = b * SCAN_BLK + tid;
    int v = (i < N_NODES) ? (g_deg[i] + 1) : 0;   // +1 = self loop
    s[tid] = v;
    __syncthreads();
    for (int off = 1; off < SCAN_BLK; off <<= 1) {
        int t = (tid >= off) ? s[tid - off] : 0;
        __syncthreads();
        s[tid] += t;
        __syncthreads();
    }
    int agg = s[SCAN_BLK - 1];

    if (tid == 0) {
        if (b == 0) {
            atomicExch(&g_scanst[0], pack_st(2u, (unsigned)agg));  // INCLUSIVE
            s_excl = 0;
        } else {
            atomicExch(&g_scanst[b], pack_st(1u, (unsigned)agg));  // AGGREGATE
            int run = 0;
            for (int j = b - 1; j >= 0; j--) {
                unsigned long long w;
                do { w = atomicAdd(&g_scanst[j], 0ULL); } while ((w >> 32) == 0ULL);
                run += (int)(w & 0xffffffffULL);
                if ((w >> 32) == 2ULL) break;                      // hit an inclusive entry
            }
            atomicExch(&g_scanst[b], pack_st(2u, (unsigned)(run + agg)));
            s_excl = run;
        }
    }
    __syncthreads();
    int excl = s_excl;

    if (i < N_NODES) {
        int incl = s[tid] + excl;
        g_rowptr[i + 1] = incl;                   // i==N-1 writes rowptr[N_NODES]
        int d = g_deg[i] + 1;
        g_deg[i] = 0;                             // self-clean for next replay
        g_cursor[i] = incl - d;
        g_isq[i] = rsqrtf((float)d);
        if (i == 0) g_rowptr[0] = 0;
    }
}

// ---------------- fill CSR ----------------
__global__ void k_fill(const void* __restrict__ ei) {
    int t = blockIdx.x * blockDim.x + threadIdx.x;
    if (t >= TOT_EDGES) return;
    int s, d;
    if (t < N_EDGES) {
        s = ld_idx(ei, t);
        d = ld_idx(ei, (size_t)N_EDGES + t);
    } else {
        s = d = t - N_EDGES;
    }
    int pos = atomicAdd(&g_cursor[d], 1);
    g_eidx[pos] = s;
}

// ---------------- tensor-core GEMM: g_hxh[N,64] = fp16(isq[n] * (X[N,K] @ W[K,64])) ----------------
template <int K, int LAYER>
__global__ void k_gemm_mma(const float* __restrict__ Xin) {
    constexpr int CK = 64;
    constexpr int APAD = 72;
    constexpr int WPAD = K + 8;
    __shared__ __half sX[128 * APAD];
    __shared__ __half sWt[64 * WPAD];

    const __half* Wt = (LAYER == 1) ? g_W1t : g_W2t;
    int tid = threadIdx.x;
    int wid = tid >> 5, lane = tid & 31;
    int g = lane >> 2, tig = lane & 3;
    int nodeBase = blockIdx.x * 128;

    for (int i = tid; i < 64 * (K / 2); i += 256) {
        int n = i / (K / 2), kw = i % (K / 2);
        ((uint32_t*)sWt)[n * (WPAD / 2) + kw] = ((const uint32_t*)Wt)[n * (K / 2) + kw];
    }

    float acc[8][4];
#pragma unroll
    for (int nt = 0; nt < 8; nt++)
#pragma unroll
        for (int j = 0; j < 4; j++) acc[nt][j] = 0.f;

    for (int kk = 0; kk < K; kk += CK) {
        for (int i = tid; i < 128 * (CK / 2); i += 256) {
            int row = i >> 5;
            int c2 = i & 31;
            int node = nodeBase + row;
            __half2 hv;
            if (LAYER == 1) {
                float2 v = (node < N_NODES)
                    ? *(const float2*)&Xin[(size_t)node * K + kk + c2 * 2]
                    : make_float2(0.f, 0.f);
                hv = __floats2half2_rn(v.x, v.y);
            } else {
                hv = (node < N_NODES)
                    ? ((const __half2*)g_h)[(size_t)node * (K / 2) + (kk / 2) + c2]
                    : __halves2half2(__float2half_rn(0.f), __float2half_rn(0.f));
            }
            ((__half2*)sX)[row * (APAD / 2) + c2] = hv;
        }
        __syncthreads();

        int mrow = wid * 16;
#pragma unroll
        for (int kt = 0; kt < CK / 16; kt++) {
            int k0 = kt * 16;
            uint32_t a0 = *(const uint32_t*)&sX[(mrow + g    ) * APAD + k0     + 2 * tig];
            uint32_t a1 = *(const uint32_t*)&sX[(mrow + g + 8) * APAD + k0     + 2 * tig];
            uint32_t a2 = *(const uint32_t*)&sX[(mrow + g    ) * APAD + k0 + 8 + 2 * tig];
            uint32_t a3 = *(const uint32_t*)&sX[(mrow + g + 8) * APAD + k0 + 8 + 2 * tig];
#pragma unroll
            for (int nt = 0; nt < 8; nt++) {
                uint32_t b0 = *(const uint32_t*)&sWt[(nt * 8 + g) * WPAD + kk + k0     + 2 * tig];
                uint32_t b1 = *(const uint32_t*)&sWt[(nt * 8 + g) * WPAD + kk + k0 + 8 + 2 * tig];
                asm volatile(
                    "mma.sync.aligned.m16n8k16.row.col.f32.f16.f16.f32 "
                    "{%0,%1,%2,%3}, {%4,%5,%6,%7}, {%8,%9}, {%0,%1,%2,%3};\n"
                    : "+f"(acc[nt][0]), "+f"(acc[nt][1]), "+f"(acc[nt][2]), "+f"(acc[nt][3])
                    : "r"(a0), "r"(a1), "r"(a2), "r"(a3), "r"(b0), "r"(b1));
            }
        }
        __syncthreads();
    }

    int r0 = nodeBase + wid * 16 + g;
    float s0 = (r0 < N_NODES) ? g_isq[r0] : 0.f;
    float s1 = (r0 + 8 < N_NODES) ? g_isq[r0 + 8] : 0.f;
#pragma unroll
    for (int nt = 0; nt < 8; nt++) {
        if (r0 < N_NODES)
            *(__half2*)&g_hxh[(size_t)r0 * 64 + nt * 8 + 2 * tig] =
                __floats2half2_rn(acc[nt][0] * s0, acc[nt][1] * s0);
        if (r0 + 8 < N_NODES)
            *(__half2*)&g_hxh[(size_t)(r0 + 8) * 64 + nt * 8 + 2 * tig] =
                __floats2half2_rn(acc[nt][2] * s1, acc[nt][3] * s1);
    }
}

// ---------------- pull aggregation: warp/node, 8-way unrolled independent gathers ----------------
template <bool FUSE_POOL>
__global__ void k_agg(const float* __restrict__ bias, const void* __restrict__ batch) {
    int gt = blockIdx.x * blockDim.x + threadIdx.x;
    int node = gt >> 5;
    int lane = gt & 31;
    int wid = threadIdx.x >> 5;

    if (!FUSE_POOL && node >= N_NODES) return;

    int r0 = g_rowptr[node];
    int r1 = g_rowptr[node + 1];
    const __half2* h2 = (const __half2*)g_hxh;

    float ax0 = 0.f, ay0 = 0.f, ax1 = 0.f, ay1 = 0.f;
    float ax2 = 0.f, ay2 = 0.f, ax3 = 0.f, ay3 = 0.f;

    int e = r0;
    for (; e + 8 <= r1; e += 8) {
        int s0 = g_eidx[e    ];
        int s1 = g_eidx[e + 1];
        int s2 = g_eidx[e + 2];
        int s3 = g_eidx[e + 3];
        int s4 = g_eidx[e + 4];
        int s5 = g_eidx[e + 5];
        int s6 = g_eidx[e + 6];
        int s7 = g_eidx[e + 7];
        float2 v0 = __half22float2(h2[(size_t)s0 * 32 + lane]);
        float2 v1 = __half22float2(h2[(size_t)s1 * 32 + lane]);
        float2 v2 = __half22float2(h2[(size_t)s2 * 32 + lane]);
        float2 v3 = __half22float2(h2[(size_t)s3 * 32 + lane]);
        float2 v4 = __half22float2(h2[(size_t)s4 * 32 + lane]);
        float2 v5 = __half22float2(h2[(size_t)s5 * 32 + lane]);
        float2 v6 = __half22float2(h2[(size_t)s6 * 32 + lane]);
        float2 v7 = __half22float2(h2[(size_t)s7 * 32 + lane]);
        ax0 += v0.x; ay0 += v0.y;
        ax1 += v1.x; ay1 += v1.y;
        ax2 += v2.x; ay2 += v2.y;
        ax3 += v3.x; ay3 += v3.y;
        ax0 += v4.x; ay0 += v4.y;
        ax1 += v5.x; ay1 += v5.y;
        ax2 += v6.x; ay2 += v6.y;
        ax3 += v7.x; ay3 += v7.y;
    }
    for (; e < r1; e++) {
        int s = g_eidx[e];
        float2 v = __half22float2(h2[(size_t)s * 32 + lane]);
        ax0 += v.x; ay0 += v.y;
    }
    float ax = (ax0 + ax1) + (ax2 + ax3);
    float ay = (ay0 + ay1) + (ay2 + ay3);

    float wd = g_isq[node];
    float ox = fmaxf(ax * wd + bias[2 * lane + 0], 0.f);
    float oy = fmaxf(ay * wd + bias[2 * lane + 1], 0.f);

    if (!FUSE_POOL) {
        ((__half2*)g_h)[(size_t)node * 32 + lane] = __floats2half2_rn(ox, oy);
    } else {
        __shared__ float s_pool[64];
        __shared__ int s_g[8];
        int gph = ld_idx(batch, node);
        if (lane == 0) s_g[wid] = gph;
        if (threadIdx.x < 64) s_pool[threadIdx.x] = 0.f;
        __syncthreads();
        if (s_g[0] == s_g[7]) {
            atomicAdd(&s_pool[2 * lane + 0], ox);
            atomicAdd(&s_pool[2 * lane + 1], oy);
            __syncthreads();
            if (threadIdx.x < 64) atomicAdd(&g_pool[s_g[0] * 64 + threadIdx.x], s_pool[threadIdx.x]);
            if (threadIdx.x == 0) atomicAdd(&g_pcnt[s_g[0]], 8.f);
        } else {
            atomicAdd(&g_pool[gph * 64 + 2 * lane + 0], ox);
            atomicAdd(&g_pool[gph * 64 + 2 * lane + 1], oy);
            if (lane == 0) atomicAdd(&g_pcnt[gph], 1.f);
        }
    }
}

// ---------------- final FC ----------------
__global__ void k_fc(const float* __restrict__ fcW, const float* __restrict__ fcb,
                     float* __restrict__ out) {
    int g = threadIdx.x;
    if (g >= G_GRAPHS) return;
    float cnt = g_pcnt[g];
    float inv = 1.f / fmaxf(cnt, 1.f);
    float a0 = fcb[0], a1 = fcb[1];
#pragma unroll
    for (int h = 0; h < 64; h++) {
        float p = g_pool[g * 64 + h] * inv;
        a0 += p * fcW[h * 2 + 0];
        a1 += p * fcW[h * 2 + 1];
    }
    out[g * 2 + 0] = a0;
    out[g * 2 + 1] = a1;
}

// ---------------- launch ----------------
extern "C" void kernel_launch(void* const* d_in, const int* in_sizes, int n_in,
                              void* d_out, int out_size) {
    const float* x    = (const float*)d_in[0];
    const void*  ei   = d_in[1];
    const void*  bat  = d_in[2];
    const float* W1   = (const float*)d_in[3];
    const float* b1   = (const float*)d_in[4];
    const float* W2   = (const float*)d_in[5];
    const float* b2   = (const float*)d_in[6];
    const float* fcW  = (const float*)d_in[7];
    const float* fcb  = (const float*)d_in[8];
    float* out = (float*)d_out;

    static cudaEvent_t evFork = nullptr, evJoin = nullptr;
    if (evFork == nullptr) {
        cudaEventCreateWithFlags(&evFork, cudaEventDisableTiming);
        cudaEventCreateWithFlags(&evJoin, cudaEventDisableTiming);
    }

    const int TPB = 256;
    int gE = (N_EDGES + TPB - 1) / TPB;              // 12500
    int gTOT = (TOT_EDGES + TPB - 1) / TPB;          // 12892
    int gW = (N_NODES * 32) / TPB;                   // 12500 exactly
    int gM = (N_NODES + 127) / 128;                  // 782

    k_setup<<<SETUP_DEG_BASE + gE, TPB>>>((const int*)ei, W1, W2);
    k_scan<<<SCAN_NB, SCAN_BLK>>>();                 // one-pass decoupled-lookback scan

    // fork: GEMM1 ∥ fill (independent; join before AGG1)
    cudaEventRecord(evFork, 0);
    cudaStreamWaitEvent(cudaStreamPerThread, evFork, 0);
    k_gemm_mma<F_IN, 1><<<gM, TPB, 0, cudaStreamPerThread>>>(x);
    k_fill<<<gTOT, TPB>>>(ei);
    cudaEventRecord(evJoin, cudaStreamPerThread);
    cudaStreamWaitEvent(0, evJoin, 0);

    k_agg<false><<<gW, TPB>>>(b1, nullptr);
    k_gemm_mma<HID, 2><<<gM, TPB>>>(nullptr);
    k_agg<true><<<gW, TPB>>>(b2, bat);
    k_fc<<<1, 128>>>(fcW, fcb, out);
}